// round 4
// baseline (speedup 1.0000x reference)
#include <cuda_runtime.h>

// Lattice constants (match reference)
#define LT 16
#define LZ 16
#define LY 16
#define LXH 8
#define DC 12          // NS*NC = 12 internal components
#define NSITE 32768    // LT*LZ*LY*LXH
#define KMAT 144       // DC*DC
#define DIAG 4.5f

// One complex 12-row dot-product contribution:
//   sr += sum_j Kr[j]*vr[j] - Ki[j]*vi[j]
//   si += sum_j Kr[j]*vi[j] + Ki[j]*vr[j]
// All pointers 16B-aligned (row byte offset i*48, site byte offset s*576/48).
__device__ __forceinline__ void cma_row(
    const float* __restrict__ Kr, const float* __restrict__ Ki,
    const float* __restrict__ vr, const float* __restrict__ vi,
    float& sr, float& si)
{
    const float4* kr4 = reinterpret_cast<const float4*>(Kr);
    const float4* ki4 = reinterpret_cast<const float4*>(Ki);
    const float4* vr4 = reinterpret_cast<const float4*>(vr);
    const float4* vi4 = reinterpret_cast<const float4*>(vi);
#pragma unroll
    for (int q = 0; q < 3; ++q) {
        float4 a = kr4[q];
        float4 b = ki4[q];
        float4 c = vr4[q];
        float4 d = vi4[q];
        sr = fmaf(a.x, c.x, sr); sr = fmaf(-b.x, d.x, sr);
        si = fmaf(a.x, d.x, si); si = fmaf( b.x, c.x, si);
        sr = fmaf(a.y, c.y, sr); sr = fmaf(-b.y, d.y, sr);
        si = fmaf(a.y, d.y, si); si = fmaf( b.y, c.y, si);
        sr = fmaf(a.z, c.z, sr); sr = fmaf(-b.z, d.z, sr);
        si = fmaf(a.z, d.z, si); si = fmaf( b.z, c.z, si);
        sr = fmaf(a.w, c.w, sr); sr = fmaf(-b.w, d.w, sr);
        si = fmaf(a.w, d.w, si); si = fmaf( b.w, c.w, si);
    }
}

__global__ __launch_bounds__(384, 2)
void hop_kernel(
    const float* __restrict__ psi_re, const float* __restrict__ psi_im,
    const float* __restrict__ Kfr,    const float* __restrict__ Kfi,
    const float* __restrict__ Kbr,    const float* __restrict__ Kbi,
    float* __restrict__ out)
{
    const int tid = blockIdx.x * 384 + threadIdx.x;
    const int s = tid / DC;      // site index
    const int i = tid % DC;      // output component (matrix row)
    if (s >= NSITE) return;

    const int x = s & 7;
    const int y = (s >> 3) & 15;
    const int z = (s >> 7) & 15;
    const int t = (s >> 11) & 15;

    // Neighbor site indices: [fwd_t, bwd_t, fwd_z, bwd_z, fwd_y, bwd_y, fwd_x, bwd_x]
    // mu<3: periodic roll; mu=3: staggered half-lattice hop gated by parity.
    int nb[8];
    nb[0] = s + ((((t + 1)  & 15) - t) << 11);
    nb[1] = s + ((((t + 15) & 15) - t) << 11);
    nb[2] = s + ((((z + 1)  & 15) - z) << 7);
    nb[3] = s + ((((z + 15) & 15) - z) << 7);
    nb[4] = s + ((((y + 1)  & 15) - y) << 3);
    nb[5] = s + ((((y + 15) & 15) - y) << 3);
    const int par = (t + z + y) & 1;
    nb[6] = par      ? (s - x + ((x + 1) & 7)) : s;  // mask_f: r==1
    nb[7] = (par==0) ? (s - x + ((x + 7) & 7)) : s;  // mask_b: r==0

    float sr = 0.0f, si = 0.0f;

    const int rowoff = i * DC;
#pragma unroll
    for (int mu = 0; mu < 4; ++mu) {
        const int kbase = (mu * NSITE + s) * KMAT + rowoff;
        // forward hop
        {
            const int v = nb[2 * mu] * DC;
            cma_row(Kfr + kbase, Kfi + kbase, psi_re + v, psi_im + v, sr, si);
        }
        // backward hop
        {
            const int v = nb[2 * mu + 1] * DC;
            cma_row(Kbr + kbase, Kbi + kbase, psi_re + v, psi_im + v, sr, si);
        }
    }

    const int o = s * DC + i;   // == tid
    out[o]               = fmaf(-0.5f, sr, DIAG * psi_re[o]);
    out[NSITE * DC + o]  = fmaf(-0.5f, si, DIAG * psi_im[o]);
}

extern "C" void kernel_launch(void* const* d_in, const int* in_sizes, int n_in,
                              void* d_out, int out_size)
{
    const float* psi_re = (const float*)d_in[0];
    const float* psi_im = (const float*)d_in[1];
    const float* Kfr    = (const float*)d_in[2];
    const float* Kfi    = (const float*)d_in[3];
    const float* Kbr    = (const float*)d_in[4];
    const float* Kbi    = (const float*)d_in[5];
    float* out = (float*)d_out;

    // 393216 threads total = 32768 sites * 12 components; 384 threads/block
    const int threads = 384;
    const int blocks = (NSITE * DC + threads - 1) / threads;  // = 1024
    hop_kernel<<<blocks, threads>>>(psi_re, psi_im, Kfr, Kfi, Kbr, Kbi, out);
}

// round 5
// speedup vs baseline: 1.0030x; 1.0030x over previous
#include <cuda_runtime.h>

// Lattice constants (match reference)
#define LT 16
#define LZ 16
#define LY 16
#define LXH 8
#define DC 12          // NS*NC = 12 internal components
#define NSITE 32768    // LT*LZ*LY*LXH
#define KMAT 144       // DC*DC
#define DIAG 4.5f

// One complex 12-row dot-product contribution:
//   sr += sum_j Kr[j]*vr[j] - Ki[j]*vi[j]
//   si += sum_j Kr[j]*vi[j] + Ki[j]*vr[j]
// All pointers 16B-aligned (row byte offset i*48, site byte offset s*576/48).
__device__ __forceinline__ void cma_row(
    const float* __restrict__ Kr, const float* __restrict__ Ki,
    const float* __restrict__ vr, const float* __restrict__ vi,
    float& sr, float& si)
{
    const float4* kr4 = reinterpret_cast<const float4*>(Kr);
    const float4* ki4 = reinterpret_cast<const float4*>(Ki);
    const float4* vr4 = reinterpret_cast<const float4*>(vr);
    const float4* vi4 = reinterpret_cast<const float4*>(vi);
#pragma unroll
    for (int q = 0; q < 3; ++q) {
        float4 a = kr4[q];
        float4 b = ki4[q];
        float4 c = vr4[q];
        float4 d = vi4[q];
        sr = fmaf(a.x, c.x, sr); sr = fmaf(-b.x, d.x, sr);
        si = fmaf(a.x, d.x, si); si = fmaf( b.x, c.x, si);
        sr = fmaf(a.y, c.y, sr); sr = fmaf(-b.y, d.y, sr);
        si = fmaf(a.y, d.y, si); si = fmaf( b.y, c.y, si);
        sr = fmaf(a.z, c.z, sr); sr = fmaf(-b.z, d.z, sr);
        si = fmaf(a.z, d.z, si); si = fmaf( b.z, c.z, si);
        sr = fmaf(a.w, c.w, sr); sr = fmaf(-b.w, d.w, sr);
        si = fmaf(a.w, d.w, si); si = fmaf( b.w, c.w, si);
    }
}

__global__ __launch_bounds__(256, 4)
void hop_kernel(
    const float* __restrict__ psi_re, const float* __restrict__ psi_im,
    const float* __restrict__ Kfr,    const float* __restrict__ Kfi,
    const float* __restrict__ Kbr,    const float* __restrict__ Kbi,
    float* __restrict__ out)
{
    const unsigned tid = blockIdx.x * 256u + threadIdx.x;
    const unsigned s = tid / DC;      // site index
    const unsigned i = tid % DC;      // output component (matrix row)
    if (s >= NSITE) return;

    const unsigned x = s & 7;
    const unsigned y = (s >> 3) & 15;
    const unsigned z = (s >> 7) & 15;
    const unsigned t = (s >> 11) & 15;

    // Neighbor site indices: [fwd_t, bwd_t, fwd_z, bwd_z, fwd_y, bwd_y, fwd_x, bwd_x]
    // mu<3: periodic roll; mu=3: staggered half-lattice hop gated by parity.
    unsigned nb[8];
    nb[0] = (s & ~(15u << 11)) | (((t + 1)  & 15) << 11);
    nb[1] = (s & ~(15u << 11)) | (((t + 15) & 15) << 11);
    nb[2] = (s & ~(15u << 7))  | (((z + 1)  & 15) << 7);
    nb[3] = (s & ~(15u << 7))  | (((z + 15) & 15) << 7);
    nb[4] = (s & ~(15u << 3))  | (((y + 1)  & 15) << 3);
    nb[5] = (s & ~(15u << 3))  | (((y + 15) & 15) << 3);
    const unsigned par = (t + z + y) & 1;
    nb[6] = par      ? ((s & ~7u) | ((x + 1) & 7)) : s;  // mask_f: r==1
    nb[7] = !par     ? ((s & ~7u) | ((x + 7) & 7)) : s;  // mask_b: r==0

    float sr = 0.0f, si = 0.0f;

    const unsigned rowoff = i * DC;
#pragma unroll
    for (int mu = 0; mu < 4; ++mu) {
        const unsigned kbase = (mu * NSITE + s) * KMAT + rowoff;
        // forward hop
        {
            const unsigned v = nb[2 * mu] * DC;
            cma_row(Kfr + kbase, Kfi + kbase, psi_re + v, psi_im + v, sr, si);
        }
        // backward hop
        {
            const unsigned v = nb[2 * mu + 1] * DC;
            cma_row(Kbr + kbase, Kbi + kbase, psi_re + v, psi_im + v, sr, si);
        }
    }

    const unsigned o = s * DC + i;   // == tid
    out[o]               = fmaf(-0.5f, sr, DIAG * psi_re[o]);
    out[NSITE * DC + o]  = fmaf(-0.5f, si, DIAG * psi_im[o]);
}

extern "C" void kernel_launch(void* const* d_in, const int* in_sizes, int n_in,
                              void* d_out, int out_size)
{
    const float* psi_re = (const float*)d_in[0];
    const float* psi_im = (const float*)d_in[1];
    const float* Kfr    = (const float*)d_in[2];
    const float* Kfi    = (const float*)d_in[3];
    const float* Kbr    = (const float*)d_in[4];
    const float* Kbi    = (const float*)d_in[5];
    float* out = (float*)d_out;

    // 393216 threads total = 32768 sites * 12 components; 256 threads/block
    const int threads = 256;
    const int blocks = (NSITE * DC + threads - 1) / threads;  // = 1536
    hop_kernel<<<blocks, threads>>>(psi_re, psi_im, Kfr, Kfi, Kbr, Kbi, out);
}

// round 6
// speedup vs baseline: 1.0808x; 1.0776x over previous
#include <cuda_runtime.h>
#include <cstdint>

#define DC 12                    // internal components
#define NSITE 32768              // 16*16*16*8
#define KMAT 144                 // 12x12
#define DIAGC 4.5f
#define SPB 16                   // sites per block
#define NTHREADS (SPB * DC)      // 192
#define STAGE_FLTS (SPB * KMAT)  // 2304 floats = 9216 B per (re) or (im)
#define STAGE_BYTES (STAGE_FLTS * 4 * 2)  // 18432 B per stage (re+im)

__device__ __forceinline__ uint32_t s2u(const void* p) {
    return (uint32_t)__cvta_generic_to_shared(p);
}

__global__ __launch_bounds__(NTHREADS)
void hop_kernel(const float* __restrict__ psi_re, const float* __restrict__ psi_im,
                const float* __restrict__ Kfr,    const float* __restrict__ Kfi,
                const float* __restrict__ Kbr,    const float* __restrict__ Kbi,
                float* __restrict__ out)
{
    __shared__ alignas(16) float kbuf[2][2][STAGE_FLTS];   // [buffer][re/im][..]
    __shared__ alignas(8) unsigned long long mbar[2];

    const int tid = threadIdx.x;
    const unsigned sbase = blockIdx.x * SPB;
    const unsigned s_loc = (unsigned)tid / DC;
    const unsigned irow  = (unsigned)tid % DC;
    const unsigned s = sbase + s_loc;

    // Lattice coords and neighbor sites.
    const unsigned x = s & 7, y = (s >> 3) & 15, z = (s >> 7) & 15, t = (s >> 11) & 15;
    unsigned nb[8];   // [fwd_t, bwd_t, fwd_z, bwd_z, fwd_y, bwd_y, fwd_x, bwd_x]
    nb[0] = (s & ~(15u << 11)) | (((t + 1)  & 15) << 11);
    nb[1] = (s & ~(15u << 11)) | (((t + 15) & 15) << 11);
    nb[2] = (s & ~(15u << 7))  | (((z + 1)  & 15) << 7);
    nb[3] = (s & ~(15u << 7))  | (((z + 15) & 15) << 7);
    nb[4] = (s & ~(15u << 3))  | (((y + 1)  & 15) << 3);
    nb[5] = (s & ~(15u << 3))  | (((y + 15) & 15) << 3);
    const unsigned par = (t + z + y) & 1;
    nb[6] = par ? ((s & ~7u) | ((x + 1) & 7)) : s;   // mask_f: r==1
    nb[7] = par ? s : ((s & ~7u) | ((x + 7) & 7));   // mask_b: r==0

    if (tid == 0) {
        asm volatile("mbarrier.init.shared.b64 [%0], %1;" :: "r"(s2u(&mbar[0])), "r"(1));
        asm volatile("mbarrier.init.shared.b64 [%0], %1;" :: "r"(s2u(&mbar[1])), "r"(1));
        asm volatile("fence.proxy.async.shared::cta;" ::: "memory");
    }
    __syncthreads();

    // Producer: issue stage st = 2*mu + dir into buffer b via 1D TMA bulk copy.
    auto issue = [&](int st, int b) {
        const unsigned off = (((unsigned)(st >> 1)) * NSITE + sbase) * KMAT;
        const float* srcR = ((st & 1) ? Kbr : Kfr) + off;
        const float* srcI = ((st & 1) ? Kbi : Kfi) + off;
        const uint32_t mb = s2u(&mbar[b]);
        asm volatile("mbarrier.arrive.expect_tx.shared.b64 _, [%0], %1;"
                     :: "r"(mb), "r"((unsigned)STAGE_BYTES) : "memory");
        asm volatile("cp.async.bulk.shared::cta.global.mbarrier::complete_tx::bytes "
                     "[%0], [%1], %2, [%3];"
                     :: "r"(s2u(&kbuf[b][0][0])), "l"(srcR),
                        "r"((unsigned)(STAGE_FLTS * 4)), "r"(mb) : "memory");
        asm volatile("cp.async.bulk.shared::cta.global.mbarrier::complete_tx::bytes "
                     "[%0], [%1], %2, [%3];"
                     :: "r"(s2u(&kbuf[b][1][0])), "l"(srcI),
                        "r"((unsigned)(STAGE_FLTS * 4)), "r"(mb) : "memory");
    };

    if (tid == 0) { issue(0, 0); issue(1, 1); }

    float sr = 0.0f, si = 0.0f;

#pragma unroll
    for (int st = 0; st < 8; ++st) {
        const int b = st & 1;
        const unsigned ph = (unsigned)(st >> 1) & 1;

        // Prefetch neighbor psi vector (L1/L2-resident) BEFORE waiting on TMA.
        const unsigned v = nb[st] * DC;
        const float4* vr4 = reinterpret_cast<const float4*>(psi_re + v);
        const float4* vi4 = reinterpret_cast<const float4*>(psi_im + v);
        const float4 c0 = vr4[0], c1 = vr4[1], c2 = vr4[2];
        const float4 d0 = vi4[0], d1 = vi4[1], d2 = vi4[2];

        // Wait for this stage's K tile.
        {
            const uint32_t mb = s2u(&mbar[b]);
            asm volatile(
                "{\n\t.reg .pred P;\n\t"
                "W%=:\n\t"
                "mbarrier.try_wait.parity.shared.b64 P, [%0], %1;\n\t"
                "@P bra D%=;\n\t"
                "bra W%=;\n\t"
                "D%=:\n\t}"
                :: "r"(mb), "r"(ph) : "memory");
        }

        // Row dot-product from smem: conflict-free LDS.128 (48 B thread stride).
        const float4* kr4 = reinterpret_cast<const float4*>(
            &kbuf[b][0][s_loc * KMAT + irow * DC]);
        const float4* ki4 = reinterpret_cast<const float4*>(
            &kbuf[b][1][s_loc * KMAT + irow * DC]);

        {
            float4 a = kr4[0], bb = ki4[0];
            sr = fmaf(a.x, c0.x, sr); sr = fmaf(-bb.x, d0.x, sr);
            si = fmaf(a.x, d0.x, si); si = fmaf( bb.x, c0.x, si);
            sr = fmaf(a.y, c0.y, sr); sr = fmaf(-bb.y, d0.y, sr);
            si = fmaf(a.y, d0.y, si); si = fmaf( bb.y, c0.y, si);
            sr = fmaf(a.z, c0.z, sr); sr = fmaf(-bb.z, d0.z, sr);
            si = fmaf(a.z, d0.z, si); si = fmaf( bb.z, c0.z, si);
            sr = fmaf(a.w, c0.w, sr); sr = fmaf(-bb.w, d0.w, sr);
            si = fmaf(a.w, d0.w, si); si = fmaf( bb.w, c0.w, si);
        }
        {
            float4 a = kr4[1], bb = ki4[1];
            sr = fmaf(a.x, c1.x, sr); sr = fmaf(-bb.x, d1.x, sr);
            si = fmaf(a.x, d1.x, si); si = fmaf( bb.x, c1.x, si);
            sr = fmaf(a.y, c1.y, sr); sr = fmaf(-bb.y, d1.y, sr);
            si = fmaf(a.y, d1.y, si); si = fmaf( bb.y, c1.y, si);
            sr = fmaf(a.z, c1.z, sr); sr = fmaf(-bb.z, d1.z, sr);
            si = fmaf(a.z, d1.z, si); si = fmaf( bb.z, c1.z, si);
            sr = fmaf(a.w, c1.w, sr); sr = fmaf(-bb.w, d1.w, sr);
            si = fmaf(a.w, d1.w, si); si = fmaf( bb.w, c1.w, si);
        }
        {
            float4 a = kr4[2], bb = ki4[2];
            sr = fmaf(a.x, c2.x, sr); sr = fmaf(-bb.x, d2.x, sr);
            si = fmaf(a.x, d2.x, si); si = fmaf( bb.x, c2.x, si);
            sr = fmaf(a.y, c2.y, sr); sr = fmaf(-bb.y, d2.y, sr);
            si = fmaf(a.y, d2.y, si); si = fmaf( bb.y, c2.y, si);
            sr = fmaf(a.z, c2.z, sr); sr = fmaf(-bb.z, d2.z, sr);
            si = fmaf(a.z, d2.z, si); si = fmaf( bb.z, c2.z, si);
            sr = fmaf(a.w, c2.w, sr); sr = fmaf(-bb.w, d2.w, sr);
            si = fmaf(a.w, d2.w, si); si = fmaf( bb.w, c2.w, si);
        }

        // All threads finished reading buffer b -> safe to refill.
        __syncthreads();
        if (st + 2 < 8 && tid == 0) issue(st + 2, b);
    }

    const unsigned o = s * DC + irow;
    out[o]              = fmaf(-0.5f, sr, DIAGC * psi_re[o]);
    out[NSITE * DC + o] = fmaf(-0.5f, si, DIAGC * psi_im[o]);
}

extern "C" void kernel_launch(void* const* d_in, const int* in_sizes, int n_in,
                              void* d_out, int out_size)
{
    const float* psi_re = (const float*)d_in[0];
    const float* psi_im = (const float*)d_in[1];
    const float* Kfr    = (const float*)d_in[2];
    const float* Kfi    = (const float*)d_in[3];
    const float* Kbr    = (const float*)d_in[4];
    const float* Kbi    = (const float*)d_in[5];
    float* out = (float*)d_out;

    hop_kernel<<<NSITE / SPB, NTHREADS>>>(psi_re, psi_im, Kfr, Kfi, Kbr, Kbi, out);
}

// round 9
// speedup vs baseline: 1.0870x; 1.0058x over previous
#include <cuda_runtime.h>
#include <cstdint>

#define DC 12                    // internal components
#define NSITE 32768              // 16*16*16*8
#define KMAT 144                 // 12x12
#define DIAGC 4.5f
#define SPB 16                   // sites per block
#define NTHREADS (SPB * DC)      // 192
#define NBUF 3                   // pipeline depth
#define STAGE_FLTS (SPB * KMAT)                // 2304 floats per (re|im) plane
#define PLANE_BYTES (STAGE_FLTS * 4)           // 9216 B
#define STAGE_BYTES (PLANE_BYTES * 2)          // 18432 B (re+im)
#define SMEM_BYTES (NBUF * STAGE_BYTES)        // 55296 B dynamic smem

__device__ __forceinline__ uint32_t s2u(const void* p) {
    return (uint32_t)__cvta_generic_to_shared(p);
}

__global__ __launch_bounds__(NTHREADS)
void hop_kernel(const float* __restrict__ psi_re, const float* __restrict__ psi_im,
                const float* __restrict__ Kfr,    const float* __restrict__ Kfi,
                const float* __restrict__ Kbr,    const float* __restrict__ Kbi,
                float* __restrict__ out)
{
    extern __shared__ float kbuf[];              // [NBUF][2][STAGE_FLTS]
    __shared__ alignas(8) unsigned long long mbar[NBUF];

    const int tid = threadIdx.x;
    const unsigned sbase = blockIdx.x * SPB;
    const unsigned s_loc = (unsigned)tid / DC;
    const unsigned irow  = (unsigned)tid % DC;
    const unsigned s = sbase + s_loc;

    // Lattice coords and neighbor sites.
    const unsigned x = s & 7, y = (s >> 3) & 15, z = (s >> 7) & 15, t = (s >> 11) & 15;
    unsigned nb[8];   // [fwd_t, bwd_t, fwd_z, bwd_z, fwd_y, bwd_y, fwd_x, bwd_x]
    nb[0] = (s & ~(15u << 11)) | (((t + 1)  & 15) << 11);
    nb[1] = (s & ~(15u << 11)) | (((t + 15) & 15) << 11);
    nb[2] = (s & ~(15u << 7))  | (((z + 1)  & 15) << 7);
    nb[3] = (s & ~(15u << 7))  | (((z + 15) & 15) << 7);
    nb[4] = (s & ~(15u << 3))  | (((y + 1)  & 15) << 3);
    nb[5] = (s & ~(15u << 3))  | (((y + 15) & 15) << 3);
    const unsigned par = (t + z + y) & 1;
    nb[6] = par ? ((s & ~7u) | ((x + 1) & 7)) : s;   // mask_f: r==1
    nb[7] = par ? s : ((s & ~7u) | ((x + 7) & 7));   // mask_b: r==0

    if (tid == 0) {
#pragma unroll
        for (int b = 0; b < NBUF; ++b)
            asm volatile("mbarrier.init.shared.b64 [%0], %1;" :: "r"(s2u(&mbar[b])), "r"(1));
        asm volatile("fence.proxy.async.shared::cta;" ::: "memory");
    }
    __syncthreads();

    // Producer: issue stage st = 2*mu + dir into buffer b via 1D TMA bulk copy.
    auto issue = [&](int st, int b) {
        const unsigned off = (((unsigned)(st >> 1)) * NSITE + sbase) * KMAT;
        const float* srcR = ((st & 1) ? Kbr : Kfr) + off;
        const float* srcI = ((st & 1) ? Kbi : Kfi) + off;
        float* dstR = kbuf + b * (2 * STAGE_FLTS);
        float* dstI = dstR + STAGE_FLTS;
        const uint32_t mb = s2u(&mbar[b]);
        asm volatile("mbarrier.arrive.expect_tx.shared.b64 _, [%0], %1;"
                     :: "r"(mb), "r"((unsigned)STAGE_BYTES) : "memory");
        asm volatile("cp.async.bulk.shared::cta.global.mbarrier::complete_tx::bytes "
                     "[%0], [%1], %2, [%3];"
                     :: "r"(s2u(dstR)), "l"(srcR),
                        "r"((unsigned)PLANE_BYTES), "r"(mb) : "memory");
        asm volatile("cp.async.bulk.shared::cta.global.mbarrier::complete_tx::bytes "
                     "[%0], [%1], %2, [%3];"
                     :: "r"(s2u(dstI)), "l"(srcI),
                        "r"((unsigned)PLANE_BYTES), "r"(mb) : "memory");
    };

    if (tid == 0) { issue(0, 0); issue(1, 1); issue(2, 2); }

    float sr = 0.0f, si = 0.0f;

#pragma unroll
    for (int st = 0; st < 8; ++st) {
        const int b = st % NBUF;
        const unsigned ph = (unsigned)(st / NBUF) & 1;

        // Prefetch neighbor psi vector (L1/L2-resident) BEFORE waiting on TMA.
        const unsigned v = nb[st] * DC;
        const float4* vr4 = reinterpret_cast<const float4*>(psi_re + v);
        const float4* vi4 = reinterpret_cast<const float4*>(psi_im + v);
        const float4 c0 = vr4[0], c1 = vr4[1], c2 = vr4[2];
        const float4 d0 = vi4[0], d1 = vi4[1], d2 = vi4[2];

        // Wait for this stage's K tile.
        {
            const uint32_t mb = s2u(&mbar[b]);
            asm volatile(
                "{\n\t.reg .pred P;\n\t"
                "W%=:\n\t"
                "mbarrier.try_wait.parity.shared.b64 P, [%0], %1;\n\t"
                "@P bra D%=;\n\t"
                "bra W%=;\n\t"
                "D%=:\n\t}"
                :: "r"(mb), "r"(ph) : "memory");
        }

        // Row dot-product from smem: conflict-free LDS.128 (48 B thread stride).
        const float* baseR = kbuf + b * (2 * STAGE_FLTS) + s_loc * KMAT + irow * DC;
        const float4* kr4 = reinterpret_cast<const float4*>(baseR);
        const float4* ki4 = reinterpret_cast<const float4*>(baseR + STAGE_FLTS);

        {
            float4 a = kr4[0], bb = ki4[0];
            sr = fmaf(a.x, c0.x, sr); sr = fmaf(-bb.x, d0.x, sr);
            si = fmaf(a.x, d0.x, si); si = fmaf( bb.x, c0.x, si);
            sr = fmaf(a.y, c0.y, sr); sr = fmaf(-bb.y, d0.y, sr);
            si = fmaf(a.y, d0.y, si); si = fmaf( bb.y, c0.y, si);
            sr = fmaf(a.z, c0.z, sr); sr = fmaf(-bb.z, d0.z, sr);
            si = fmaf(a.z, d0.z, si); si = fmaf( bb.z, c0.z, si);
            sr = fmaf(a.w, c0.w, sr); sr = fmaf(-bb.w, d0.w, sr);
            si = fmaf(a.w, d0.w, si); si = fmaf( bb.w, c0.w, si);
        }
        {
            float4 a = kr4[1], bb = ki4[1];
            sr = fmaf(a.x, c1.x, sr); sr = fmaf(-bb.x, d1.x, sr);
            si = fmaf(a.x, d1.x, si); si = fmaf( bb.x, c1.x, si);
            sr = fmaf(a.y, c1.y, sr); sr = fmaf(-bb.y, d1.y, sr);
            si = fmaf(a.y, d1.y, si); si = fmaf( bb.y, c1.y, si);
            sr = fmaf(a.z, c1.z, sr); sr = fmaf(-bb.z, d1.z, sr);
            si = fmaf(a.z, d1.z, si); si = fmaf( bb.z, c1.z, si);
            sr = fmaf(a.w, c1.w, sr); sr = fmaf(-bb.w, d1.w, sr);
            si = fmaf(a.w, d1.w, si); si = fmaf( bb.w, c1.w, si);
        }
        {
            float4 a = kr4[2], bb = ki4[2];
            sr = fmaf(a.x, c2.x, sr); sr = fmaf(-bb.x, d2.x, sr);
            si = fmaf(a.x, d2.x, si); si = fmaf( bb.x, c2.x, si);
            sr = fmaf(a.y, c2.y, sr); sr = fmaf(-bb.y, d2.y, sr);
            si = fmaf(a.y, d2.y, si); si = fmaf( bb.y, c2.y, si);
            sr = fmaf(a.z, c2.z, sr); sr = fmaf(-bb.z, d2.z, sr);
            si = fmaf(a.z, d2.z, si); si = fmaf( bb.z, c2.z, si);
            sr = fmaf(a.w, c2.w, sr); sr = fmaf(-bb.w, d2.w, sr);
            si = fmaf(a.w, d2.w, si); si = fmaf( bb.w, c2.w, si);
        }

        // All threads finished reading buffer b -> safe to refill.
        __syncthreads();
        if (st + NBUF < 8 && tid == 0) issue(st + NBUF, b);
    }

    const unsigned o = s * DC + irow;
    out[o]              = fmaf(-0.5f, sr, DIAGC * psi_re[o]);
    out[NSITE * DC + o] = fmaf(-0.5f, si, DIAGC * psi_im[o]);
}

extern "C" void kernel_launch(void* const* d_in, const int* in_sizes, int n_in,
                              void* d_out, int out_size)
{
    const float* psi_re = (const float*)d_in[0];
    const float* psi_im = (const float*)d_in[1];
    const float* Kfr    = (const float*)d_in[2];
    const float* Kfi    = (const float*)d_in[3];
    const float* Kbr    = (const float*)d_in[4];
    const float* Kbi    = (const float*)d_in[5];
    float* out = (float*)d_out;

    // >48KB dynamic smem requires the opt-in attribute (deterministic, no alloc).
    cudaFuncSetAttribute(hop_kernel, cudaFuncAttributeMaxDynamicSharedMemorySize,
                         SMEM_BYTES);
    hop_kernel<<<NSITE / SPB, NTHREADS, SMEM_BYTES>>>(
        psi_re, psi_im, Kfr, Kfi, Kbr, Kbi, out);
}